// round 8
// baseline (speedup 1.0000x reference)
#include <cuda_runtime.h>
#include <cstdint>

// SMPL forward kinematics, HBM-bound. Round 8:
// Round-7's cp.async.bulk pipeline deepened: 4-slot ring buffer per block,
// 3 tiles in flight at all times, so bulk-engine completion jitter no longer
// exposes waits. NB=8 tiles keep 4 slots within 27.7 KB -> 8 blocks/SM.
//
// Math (G-conjugations cancel):
//   out[b,j] = out[b,P[j]] + R_{b,P[j]} * v_j,  out[b,0] = 0
//   v_j = (off[j][1], off[j][2], off[j][0])   (fixed constants, hardcoded)

#define NB     8                   // batches per tile
#define TF4    (NB * 54)           // float4 per input tile (432)
#define TO4    (NB * 18)           // float4 per output tile (144)
#define TILEB  (TF4 * 16)          // 6,912 bytes per input tile
#define NSTAGE 4                   // ring slots (depth-3 prefetch)
#define BLKS_PER_SM 8
#define GRID   (152 * BLKS_PER_SM) // 1216 persistent blocks

// v_j = G * off_j, from the reference's constant SMPL_OFFSETS
__device__ constexpr float VXC[24] = {0.f, 0.0372f, 0.0276f, -0.0094f, 0.0261f, -0.0383f,
    -0.0275f, 0.0121f, -0.0221f, 0.0028f, 0.0028f, -0.0014f, -0.0085f, 0.0064f, 0.0455f,
    0.078f, 0.1621f, 0.1687f, 0.055f, -0.0527f, -0.0719f, -0.1651f, -0.1708f, -0.0563f};
__device__ constexpr float VYC[24] = {0.f, -0.0522f, -0.2453f, -0.271f, -0.0383f, -0.0575f,
    -0.2436f, -0.2666f, -0.0394f, 0.079f, 0.0876f, 0.0356f, 0.1343f, 0.0565f, 0.0724f,
    0.0287f, -0.0099f, 0.0081f, -0.0068f, 0.0714f, 0.0297f, -0.0091f, 0.0043f, -0.0055f};
__device__ constexpr float VZC[24] = {0.f, -0.0112f, 0.0051f, -0.0238f, 0.0775f, -0.0086f,
    -0.0031f, -0.0219f, 0.0827f, -0.0244f, 0.017f, 0.0018f, -0.0212f, 0.032f, -0.012f,
    -0.0121f, -0.0146f, -0.0047f, -0.0099f, -0.015f, -0.0054f, -0.0198f, -0.0038f, -0.0064f};

__device__ __forceinline__ void mbar_init(uint32_t mb, uint32_t cnt) {
    asm volatile("mbarrier.init.shared::cta.b64 [%0], %1;" :: "r"(mb), "r"(cnt) : "memory");
}
__device__ __forceinline__ void bulk_load(uint32_t dst, const void* src, uint32_t bytes, uint32_t mb) {
    asm volatile("mbarrier.arrive.expect_tx.shared::cta.b64 _, [%0], %1;" :: "r"(mb), "r"(bytes) : "memory");
    asm volatile("cp.async.bulk.shared::cta.global.mbarrier::complete_tx::bytes [%0], [%1], %2, [%3];"
                 :: "r"(dst), "l"(src), "r"(bytes), "r"(mb) : "memory");
}
__device__ __forceinline__ void mbar_wait(uint32_t mb, uint32_t parity) {
    uint32_t done;
    asm volatile("{\n .reg .pred p;\n"
                 " mbarrier.try_wait.parity.acquire.cta.shared::cta.b64 p, [%1], %2;\n"
                 " selp.b32 %0, 1, 0, p;\n}"
                 : "=r"(done) : "r"(mb), "r"(parity) : "memory");
    if (!done) {
        asm volatile("{\n .reg .pred P1;\n"
                     "W%=:\n"
                     " mbarrier.try_wait.parity.acquire.cta.shared::cta.b64 P1, [%0], %1, 0x989680;\n"
                     " @P1 bra.uni D%=;\n"
                     " bra.uni W%=;\n"
                     "D%=:\n}"
                     :: "r"(mb), "r"(parity) : "memory");
    }
}

__global__ __launch_bounds__(32, BLKS_PER_SM)
void smpl_fk_kernel(const float4* __restrict__ orient,
                    float4*       __restrict__ out,
                    int Btotal)
{
    __shared__ __align__(1024) float4 buf[NSTAGE * TF4];      // 27,648 B ring
    __shared__ __align__(8)  unsigned long long mbars[NSTAGE];
    const int tid    = threadIdx.x;
    const int nTiles = (Btotal + NB - 1) / NB;
    const int t0     = blockIdx.x;
    if (t0 >= nTiles) return;

    uint32_t bufAddr, mbAddr;
    asm("{ .reg .u64 u; cvta.to.shared.u64 u, %1; cvt.u32.u64 %0, u; }" : "=r"(bufAddr) : "l"(buf));
    asm("{ .reg .u64 u; cvta.to.shared.u64 u, %1; cvt.u32.u64 %0, u; }" : "=r"(mbAddr)  : "l"(mbars));

    if (tid == 0) {
#pragma unroll
        for (int s = 0; s < NSTAGE; ++s) mbar_init(mbAddr + 8u * s, 1);
        asm volatile("fence.proxy.async.shared::cta;" ::: "memory");
    }
    __syncthreads();

    auto tile_bytes = [&](int tile) -> uint32_t {
        const int nb = (Btotal - tile * NB < NB) ? (Btotal - tile * NB) : NB;
        return (uint32_t)nb * 54u * 16u;
    };

    // prime slots 0..2 with tiles t0, t0+G, t0+2G
    if (tid == 0) {
#pragma unroll
        for (int k = 0; k < NSTAGE - 1; ++k) {
            const int tk = t0 + k * GRID;
            if (tk < nTiles)
                bulk_load(bufAddr + (uint32_t)k * TILEB,
                          orient + (long long)tk * TF4, tile_bytes(tk),
                          mbAddr + 8u * k);
        }
    }

    for (int i = 0; ; ++i) {
        const int tcur = t0 + i * GRID;
        if (tcur >= nTiles) break;
        const int slot = i & (NSTAGE - 1);

        // issue depth-3 prefetch into the slot consumed 1 iteration ago
        {
            const int tpre = t0 + (i + NSTAGE - 1) * GRID;
            if (tpre < nTiles && tid == 0) {
                asm volatile("fence.proxy.async.shared::cta;" ::: "memory");
                const int ps = (i + NSTAGE - 1) & (NSTAGE - 1);
                bulk_load(bufAddr + (uint32_t)ps * TILEB,
                          orient + (long long)tpre * TF4, tile_bytes(tpre),
                          mbAddr + 8u * ps);
            }
        }

        // wait for current slot (slot waited at i ≡ slot mod 4 -> parity (i>>2)&1)
        mbar_wait(mbAddr + 8u * slot, (i >> 2) & 1);
        __syncthreads();

        const float4* sb = buf + slot * TF4;      // batch-major records, 54 float4 each
        const int nb = (Btotal - tcur * NB < NB) ? (Btotal - tcur * NB) : NB;

        // ---------------- compute: lanes 0..7, one batch each (AoS smem reads) ----
        float px[24], py[24], pz[24];
        if (tid < nb) {
            const float4* rec = sb + tid * 54;
            constexpr int PAR[24] = {-1,0,1,2,3,0,5,6,7,0,9,10,11,12,11,14,15,16,17,11,19,20,21,22};
            px[0] = 0.f; py[0] = 0.f; pz[0] = 0.f;
#pragma unroll
            for (int j = 1; j < 24; ++j) {
                const int p  = PAR[j];
                const int w0 = 9 * p;      // first word of matrix p in the record
                const int c0 = w0 >> 2;    // float4 chunk (compile-time)
                const int r  = w0 & 3;     // word offset (compile-time)

                const float4 A = rec[c0 + 0];
                const float4 Bq= rec[c0 + 1];
                const float4 C = rec[c0 + 2];
                float m[12];
                m[0]=A.x;  m[1]=A.y;  m[2]=A.z;  m[3]=A.w;
                m[4]=Bq.x; m[5]=Bq.y; m[6]=Bq.z; m[7]=Bq.w;
                m[8]=C.x;  m[9]=C.y;  m[10]=C.z; m[11]=C.w;

                px[j] = fmaf(m[r+0], VXC[j], fmaf(m[r+1], VYC[j], fmaf(m[r+2], VZC[j], px[p])));
                py[j] = fmaf(m[r+3], VXC[j], fmaf(m[r+4], VYC[j], fmaf(m[r+5], VZC[j], py[p])));
                pz[j] = fmaf(m[r+6], VXC[j], fmaf(m[r+7], VYC[j], fmaf(m[r+8], VZC[j], pz[p])));
            }
        }
        __syncthreads();   // record reads done before staging overwrites the slot

        // ---------------- stage out: batch-major output into head of consumed slot
        {
            float* sow = (float*)(buf + slot * TF4);
            if (tid < nb) {
                float* dst = sow + tid * 72;       // 24 joints * 3 words, contiguous
#pragma unroll
                for (int j = 0; j < 24; ++j) {
                    dst[3 * j + 0] = px[j];
                    dst[3 * j + 1] = py[j];
                    dst[3 * j + 2] = pz[j];
                }
            }
        }
        __syncthreads();

        // ---------------- write out: straight coalesced smem -> gmem copy ----------
        {
            const float4* so = buf + slot * TF4;
            float4* obase = out + (long long)tcur * TO4;
            const int total = nb * 18;
#pragma unroll
            for (int it = 0; it < (TO4 + 31) / 32; ++it) {   // 5 iterations
                const int g = it * 32 + tid;
                if (g < total) obase[g] = so[g];
            }
        }
        __syncthreads();   // slot fully consumed before it becomes a load target again
    }
}

extern "C" void kernel_launch(void* const* d_in, const int* in_sizes, int n_in,
                              void* d_out, int out_size)
{
    const float4* orient = (const float4*)d_in[0];   // (B, 24, 3, 3) fp32
    float4*       out    = (float4*)d_out;           // (B, 24, 3) fp32

    const int B = in_sizes[0] / 216;
    const int nTiles = (B + NB - 1) / NB;
    const int grid = (nTiles < GRID) ? nTiles : GRID;

    cudaFuncSetAttribute(smpl_fk_kernel,
                         cudaFuncAttributePreferredSharedMemoryCarveout, 100);
    smpl_fk_kernel<<<grid, 32>>>(orient, out, B);
}

// round 9
// speedup vs baseline: 1.0218x; 1.0218x over previous
#include <cuda_runtime.h>
#include <cstdint>

// SMPL forward kinematics, HBM-bound. Round 9:
// R7's cp.async.bulk big-tile pipeline with true depth-3: NB=14 tiles,
// 3-slot ring, 6 persistent single-warp blocks/SM (217.7 KB smem/SM).
// Block always has ~2 tiles queued on the bulk engine -> no queue-drain gaps.
//
// Math (G-conjugations cancel):
//   out[b,j] = out[b,P[j]] + R_{b,P[j]} * v_j,  out[b,0] = 0
//   v_j = (off[j][1], off[j][2], off[j][0])   (fixed constants, hardcoded)

#define NB     14                  // batches per tile
#define TF4    (NB * 54)           // float4 per input tile (756)
#define TO4    (NB * 18)           // float4 per output tile (252)
#define TILEB  (TF4 * 16)          // 12,096 bytes per input tile
#define NSLOT  3                   // ring slots (depth-3 prefetch)
#define BLKS_PER_SM 6
#define GRID   (152 * BLKS_PER_SM) // 912 persistent blocks

// v_j = G * off_j, from the reference's constant SMPL_OFFSETS
__device__ constexpr float VXC[24] = {0.f, 0.0372f, 0.0276f, -0.0094f, 0.0261f, -0.0383f,
    -0.0275f, 0.0121f, -0.0221f, 0.0028f, 0.0028f, -0.0014f, -0.0085f, 0.0064f, 0.0455f,
    0.078f, 0.1621f, 0.1687f, 0.055f, -0.0527f, -0.0719f, -0.1651f, -0.1708f, -0.0563f};
__device__ constexpr float VYC[24] = {0.f, -0.0522f, -0.2453f, -0.271f, -0.0383f, -0.0575f,
    -0.2436f, -0.2666f, -0.0394f, 0.079f, 0.0876f, 0.0356f, 0.1343f, 0.0565f, 0.0724f,
    0.0287f, -0.0099f, 0.0081f, -0.0068f, 0.0714f, 0.0297f, -0.0091f, 0.0043f, -0.0055f};
__device__ constexpr float VZC[24] = {0.f, -0.0112f, 0.0051f, -0.0238f, 0.0775f, -0.0086f,
    -0.0031f, -0.0219f, 0.0827f, -0.0244f, 0.017f, 0.0018f, -0.0212f, 0.032f, -0.012f,
    -0.0121f, -0.0146f, -0.0047f, -0.0099f, -0.015f, -0.0054f, -0.0198f, -0.0038f, -0.0064f};

__device__ __forceinline__ void mbar_init(uint32_t mb, uint32_t cnt) {
    asm volatile("mbarrier.init.shared::cta.b64 [%0], %1;" :: "r"(mb), "r"(cnt) : "memory");
}
__device__ __forceinline__ void bulk_load(uint32_t dst, const void* src, uint32_t bytes, uint32_t mb) {
    asm volatile("mbarrier.arrive.expect_tx.shared::cta.b64 _, [%0], %1;" :: "r"(mb), "r"(bytes) : "memory");
    asm volatile("cp.async.bulk.shared::cta.global.mbarrier::complete_tx::bytes [%0], [%1], %2, [%3];"
                 :: "r"(dst), "l"(src), "r"(bytes), "r"(mb) : "memory");
}
__device__ __forceinline__ void mbar_wait(uint32_t mb, uint32_t parity) {
    uint32_t done;
    asm volatile("{\n .reg .pred p;\n"
                 " mbarrier.try_wait.parity.acquire.cta.shared::cta.b64 p, [%1], %2;\n"
                 " selp.b32 %0, 1, 0, p;\n}"
                 : "=r"(done) : "r"(mb), "r"(parity) : "memory");
    if (!done) {
        asm volatile("{\n .reg .pred P1;\n"
                     "W%=:\n"
                     " mbarrier.try_wait.parity.acquire.cta.shared::cta.b64 P1, [%0], %1, 0x989680;\n"
                     " @P1 bra.uni D%=;\n"
                     " bra.uni W%=;\n"
                     "D%=:\n}"
                     :: "r"(mb), "r"(parity) : "memory");
    }
}

__global__ __launch_bounds__(32, BLKS_PER_SM)
void smpl_fk_kernel(const float4* __restrict__ orient,
                    float4*       __restrict__ out,
                    int Btotal)
{
    __shared__ __align__(1024) float4 buf[NSLOT * TF4];      // 36,288 B ring
    __shared__ __align__(8)  unsigned long long mbars[NSLOT];
    const int tid    = threadIdx.x;
    const int nTiles = (Btotal + NB - 1) / NB;
    const int t0     = blockIdx.x;
    if (t0 >= nTiles) return;

    uint32_t bufAddr, mbAddr;
    asm("{ .reg .u64 u; cvta.to.shared.u64 u, %1; cvt.u32.u64 %0, u; }" : "=r"(bufAddr) : "l"(buf));
    asm("{ .reg .u64 u; cvta.to.shared.u64 u, %1; cvt.u32.u64 %0, u; }" : "=r"(mbAddr)  : "l"(mbars));

    if (tid == 0) {
#pragma unroll
        for (int s = 0; s < NSLOT; ++s) mbar_init(mbAddr + 8u * s, 1);
        asm volatile("fence.proxy.async.shared::cta;" ::: "memory");
    }
    __syncthreads();

    auto tile_bytes = [&](int tile) -> uint32_t {
        const int nb = (Btotal - tile * NB < NB) ? (Btotal - tile * NB) : NB;
        return (uint32_t)nb * 54u * 16u;
    };

    // prime slots 0,1 with tiles t0, t0+G (slot 2 filled at iter 0's top)
    if (tid == 0) {
#pragma unroll
        for (int k = 0; k < 2; ++k) {
            const int tk = t0 + k * GRID;
            if (tk < nTiles)
                bulk_load(bufAddr + (uint32_t)k * TILEB,
                          orient + (long long)tk * TF4, tile_bytes(tk),
                          mbAddr + 8u * k);
        }
    }

    for (int i = 0; ; ++i) {
        const int tcur = t0 + i * GRID;
        if (tcur >= nTiles) break;
        const int slot = i % NSLOT;

        // depth-3 prefetch: tile i+2 into slot (i+2)%NSLOT (consumed at iter i-1)
        {
            const int tpre = t0 + (i + 2) * GRID;
            if (tpre < nTiles && tid == 0) {
                asm volatile("fence.proxy.async.shared::cta;" ::: "memory");
                const int ps = (i + 2) % NSLOT;
                bulk_load(bufAddr + (uint32_t)ps * TILEB,
                          orient + (long long)tpre * TF4, tile_bytes(tpre),
                          mbAddr + 8u * ps);
            }
        }

        // wait for current slot; k-th use of a slot has parity k&1, k = i/NSLOT
        mbar_wait(mbAddr + 8u * slot, (i / NSLOT) & 1);
        // no __syncthreads needed: every thread polled the mbarrier itself

        const float4* sb = buf + slot * TF4;      // batch-major records, 54 float4 each
        const int nb = (Btotal - tcur * NB < NB) ? (Btotal - tcur * NB) : NB;

        // ---------------- compute: lanes 0..13, one batch each (AoS smem reads) ----
        float px[24], py[24], pz[24];
        if (tid < nb) {
            const float4* rec = sb + tid * 54;
            constexpr int PAR[24] = {-1,0,1,2,3,0,5,6,7,0,9,10,11,12,11,14,15,16,17,11,19,20,21,22};
            px[0] = 0.f; py[0] = 0.f; pz[0] = 0.f;
#pragma unroll
            for (int j = 1; j < 24; ++j) {
                const int p  = PAR[j];
                const int w0 = 9 * p;      // first word of matrix p in the record
                const int c0 = w0 >> 2;    // float4 chunk (compile-time)
                const int r  = w0 & 3;     // word offset (compile-time)

                const float4 A = rec[c0 + 0];
                const float4 Bq= rec[c0 + 1];
                const float4 C = rec[c0 + 2];
                float m[12];
                m[0]=A.x;  m[1]=A.y;  m[2]=A.z;  m[3]=A.w;
                m[4]=Bq.x; m[5]=Bq.y; m[6]=Bq.z; m[7]=Bq.w;
                m[8]=C.x;  m[9]=C.y;  m[10]=C.z; m[11]=C.w;

                px[j] = fmaf(m[r+0], VXC[j], fmaf(m[r+1], VYC[j], fmaf(m[r+2], VZC[j], px[p])));
                py[j] = fmaf(m[r+3], VXC[j], fmaf(m[r+4], VYC[j], fmaf(m[r+5], VZC[j], py[p])));
                pz[j] = fmaf(m[r+6], VXC[j], fmaf(m[r+7], VYC[j], fmaf(m[r+8], VZC[j], pz[p])));
            }
        }
        __syncthreads();   // record reads done before staging overwrites the slot

        // ---------------- stage out: batch-major output into head of consumed slot
        {
            float* sow = (float*)(buf + slot * TF4);
            if (tid < nb) {
                float* dst = sow + tid * 72;       // 24 joints * 3 words, contiguous
#pragma unroll
                for (int j = 0; j < 24; ++j) {
                    dst[3 * j + 0] = px[j];
                    dst[3 * j + 1] = py[j];
                    dst[3 * j + 2] = pz[j];
                }
            }
        }
        __syncthreads();

        // ---------------- write out: straight coalesced smem -> gmem copy ----------
        {
            const float4* so = buf + slot * TF4;
            float4* obase = out + (long long)tcur * TO4;
            const int total = nb * 18;
#pragma unroll
            for (int it = 0; it < (TO4 + 31) / 32; ++it) {   // 8 iterations
                const int g = it * 32 + tid;
                if (g < total) obase[g] = so[g];
            }
        }
        __syncthreads();   // slot fully consumed before it becomes a load target again
    }
}

extern "C" void kernel_launch(void* const* d_in, const int* in_sizes, int n_in,
                              void* d_out, int out_size)
{
    const float4* orient = (const float4*)d_in[0];   // (B, 24, 3, 3) fp32
    float4*       out    = (float4*)d_out;           // (B, 24, 3) fp32

    const int B = in_sizes[0] / 216;
    const int nTiles = (B + NB - 1) / NB;
    const int grid = (nTiles < GRID) ? nTiles : GRID;

    cudaFuncSetAttribute(smpl_fk_kernel,
                         cudaFuncAttributePreferredSharedMemoryCarveout, 100);
    smpl_fk_kernel<<<grid, 32>>>(orient, out, B);
}

// round 10
// speedup vs baseline: 1.1606x; 1.1358x over previous
#include <cuda_runtime.h>
#include <cstdint>

// SMPL forward kinematics, HBM-bound. Round 10:
// Both directions on the async bulk engine: cp.async.bulk loads (R7) AND
// cp.async.bulk stores for the output. 8 persistent single-warp blocks/SM,
// 3-slot ring with depth-1 prefetch; the third slot gives each pending bulk
// store a full iteration of slack (bulk.wait_group 1 at loop top).
//
// Math (G-conjugations cancel):
//   out[b,j] = out[b,P[j]] + R_{b,P[j]} * v_j,  out[b,0] = 0
//   v_j = (off[j][1], off[j][2], off[j][0])   (fixed constants, hardcoded)

#define NB     10                  // batches per tile
#define TF4    (NB * 54)           // float4 per input tile (540)
#define TO4    (NB * 18)           // float4 per output tile (180)
#define TILEB  (TF4 * 16)          // 8,640 bytes per input tile
#define NSLOT  3                   // ring slots (1 load-ahead + 1 store-slack)
#define BLKS_PER_SM 8
#define GRID   (152 * BLKS_PER_SM) // 1216 persistent blocks

// v_j = G * off_j, from the reference's constant SMPL_OFFSETS
__device__ constexpr float VXC[24] = {0.f, 0.0372f, 0.0276f, -0.0094f, 0.0261f, -0.0383f,
    -0.0275f, 0.0121f, -0.0221f, 0.0028f, 0.0028f, -0.0014f, -0.0085f, 0.0064f, 0.0455f,
    0.078f, 0.1621f, 0.1687f, 0.055f, -0.0527f, -0.0719f, -0.1651f, -0.1708f, -0.0563f};
__device__ constexpr float VYC[24] = {0.f, -0.0522f, -0.2453f, -0.271f, -0.0383f, -0.0575f,
    -0.2436f, -0.2666f, -0.0394f, 0.079f, 0.0876f, 0.0356f, 0.1343f, 0.0565f, 0.0724f,
    0.0287f, -0.0099f, 0.0081f, -0.0068f, 0.0714f, 0.0297f, -0.0091f, 0.0043f, -0.0055f};
__device__ constexpr float VZC[24] = {0.f, -0.0112f, 0.0051f, -0.0238f, 0.0775f, -0.0086f,
    -0.0031f, -0.0219f, 0.0827f, -0.0244f, 0.017f, 0.0018f, -0.0212f, 0.032f, -0.012f,
    -0.0121f, -0.0146f, -0.0047f, -0.0099f, -0.015f, -0.0054f, -0.0198f, -0.0038f, -0.0064f};

__device__ __forceinline__ void mbar_init(uint32_t mb, uint32_t cnt) {
    asm volatile("mbarrier.init.shared::cta.b64 [%0], %1;" :: "r"(mb), "r"(cnt) : "memory");
}
__device__ __forceinline__ void bulk_load(uint32_t dst, const void* src, uint32_t bytes, uint32_t mb) {
    asm volatile("mbarrier.arrive.expect_tx.shared::cta.b64 _, [%0], %1;" :: "r"(mb), "r"(bytes) : "memory");
    asm volatile("cp.async.bulk.shared::cta.global.mbarrier::complete_tx::bytes [%0], [%1], %2, [%3];"
                 :: "r"(dst), "l"(src), "r"(bytes), "r"(mb) : "memory");
}
__device__ __forceinline__ void bulk_store(void* dst, uint32_t src, uint32_t bytes) {
    asm volatile("cp.async.bulk.global.shared::cta.bulk_group [%0], [%1], %2;"
                 :: "l"(dst), "r"(src), "r"(bytes) : "memory");
    asm volatile("cp.async.bulk.commit_group;" ::: "memory");
}
template<int N> __device__ __forceinline__ void bulk_store_wait() {
    asm volatile("cp.async.bulk.wait_group %0;" :: "n"(N) : "memory");
}
__device__ __forceinline__ void mbar_wait(uint32_t mb, uint32_t parity) {
    uint32_t done;
    asm volatile("{\n .reg .pred p;\n"
                 " mbarrier.try_wait.parity.acquire.cta.shared::cta.b64 p, [%1], %2;\n"
                 " selp.b32 %0, 1, 0, p;\n}"
                 : "=r"(done) : "r"(mb), "r"(parity) : "memory");
    if (!done) {
        asm volatile("{\n .reg .pred P1;\n"
                     "W%=:\n"
                     " mbarrier.try_wait.parity.acquire.cta.shared::cta.b64 P1, [%0], %1, 0x989680;\n"
                     " @P1 bra.uni D%=;\n"
                     " bra.uni W%=;\n"
                     "D%=:\n}"
                     :: "r"(mb), "r"(parity) : "memory");
    }
}

__global__ __launch_bounds__(32, BLKS_PER_SM)
void smpl_fk_kernel(const float4* __restrict__ orient,
                    float4*       __restrict__ out,
                    int Btotal)
{
    __shared__ __align__(1024) float4 buf[NSLOT * TF4];      // 25,920 B ring
    __shared__ __align__(8)  unsigned long long mbars[NSLOT];
    const int tid    = threadIdx.x;
    const int nTiles = (Btotal + NB - 1) / NB;
    const int t0     = blockIdx.x;
    if (t0 >= nTiles) return;

    uint32_t bufAddr, mbAddr;
    asm("{ .reg .u64 u; cvta.to.shared.u64 u, %1; cvt.u32.u64 %0, u; }" : "=r"(bufAddr) : "l"(buf));
    asm("{ .reg .u64 u; cvta.to.shared.u64 u, %1; cvt.u32.u64 %0, u; }" : "=r"(mbAddr)  : "l"(mbars));

    if (tid == 0) {
#pragma unroll
        for (int s = 0; s < NSLOT; ++s) mbar_init(mbAddr + 8u * s, 1);
        asm volatile("fence.proxy.async.shared::cta;" ::: "memory");
    }
    __syncthreads();

    auto tile_nb = [&](int tile) -> int {
        const int r = Btotal - tile * NB;
        return (r < NB) ? r : NB;
    };

    // prime slot 0 with tile t0
    if (tid == 0)
        bulk_load(bufAddr, orient + (long long)t0 * TF4,
                  (uint32_t)tile_nb(t0) * 54u * 16u, mbAddr);

    for (int i = 0; ; ++i) {
        const int tcur = t0 + i * GRID;
        if (tcur >= nTiles) break;
        const int slot = i % NSLOT;

        // depth-1 prefetch: tile i+1 into slot (i+1)%3.
        // bulk.wait_group 1 first: that slot's pending store (issued at the end
        // of iter i-2) must have drained before the load overwrites it.
        {
            const int tpre = t0 + (i + 1) * GRID;
            if (tpre < nTiles && tid == 0) {
                bulk_store_wait<1>();
                const int ps = (i + 1) % NSLOT;
                bulk_load(bufAddr + (uint32_t)ps * TILEB,
                          orient + (long long)tpre * TF4,
                          (uint32_t)tile_nb(tpre) * 54u * 16u,
                          mbAddr + 8u * ps);
            }
        }

        // wait for current slot; k-th use of a slot has parity k&1, k = i/NSLOT
        mbar_wait(mbAddr + 8u * slot, (i / NSLOT) & 1);

        const float4* sb = buf + slot * TF4;      // batch-major records, 54 float4 each
        const int nb = tile_nb(tcur);

        // ---------------- compute: lanes 0..9, one batch each (AoS smem reads) ----
        float px[24], py[24], pz[24];
        if (tid < nb) {
            const float4* rec = sb + tid * 54;
            constexpr int PAR[24] = {-1,0,1,2,3,0,5,6,7,0,9,10,11,12,11,14,15,16,17,11,19,20,21,22};
            px[0] = 0.f; py[0] = 0.f; pz[0] = 0.f;
#pragma unroll
            for (int j = 1; j < 24; ++j) {
                const int p  = PAR[j];
                const int w0 = 9 * p;      // first word of matrix p in the record
                const int c0 = w0 >> 2;    // float4 chunk (compile-time)
                const int r  = w0 & 3;     // word offset (compile-time)

                const float4 A = rec[c0 + 0];
                const float4 Bq= rec[c0 + 1];
                const float4 C = rec[c0 + 2];
                float m[12];
                m[0]=A.x;  m[1]=A.y;  m[2]=A.z;  m[3]=A.w;
                m[4]=Bq.x; m[5]=Bq.y; m[6]=Bq.z; m[7]=Bq.w;
                m[8]=C.x;  m[9]=C.y;  m[10]=C.z; m[11]=C.w;

                px[j] = fmaf(m[r+0], VXC[j], fmaf(m[r+1], VYC[j], fmaf(m[r+2], VZC[j], px[p])));
                py[j] = fmaf(m[r+3], VXC[j], fmaf(m[r+4], VYC[j], fmaf(m[r+5], VZC[j], py[p])));
                pz[j] = fmaf(m[r+6], VXC[j], fmaf(m[r+7], VYC[j], fmaf(m[r+8], VZC[j], pz[p])));
            }
        }
        __syncthreads();   // record reads done before staging overwrites the slot
                           // (also orders this iter after tid0's wait_group above)

        // ---------------- stage out: batch-major output into head of consumed slot
        {
            float* sow = (float*)(buf + slot * TF4);
            if (tid < nb) {
                float* dst = sow + tid * 72;       // 24 joints * 3 words, contiguous
#pragma unroll
                for (int j = 0; j < 24; ++j) {
                    dst[3 * j + 0] = px[j];
                    dst[3 * j + 1] = py[j];
                    dst[3 * j + 2] = pz[j];
                }
            }
        }
        __syncthreads();   // staging visible before the async-proxy store reads it

        // ---------------- async bulk store: slot head -> gmem ----------------------
        if (tid == 0) {
            asm volatile("fence.proxy.async.shared::cta;" ::: "memory");
            bulk_store(out + (long long)tcur * TO4,
                       bufAddr + (uint32_t)slot * TILEB,
                       (uint32_t)nb * 72u * 4u);
        }
        // no trailing barrier: next slot's mbar_wait gates the other threads,
        // and slot-reuse hazards are covered by bulk_store_wait at loop top.
    }

    if (tid == 0) bulk_store_wait<0>();   // all stores complete before exit
}

extern "C" void kernel_launch(void* const* d_in, const int* in_sizes, int n_in,
                              void* d_out, int out_size)
{
    const float4* orient = (const float4*)d_in[0];   // (B, 24, 3, 3) fp32
    float4*       out    = (float4*)d_out;           // (B, 24, 3) fp32

    const int B = in_sizes[0] / 216;
    const int nTiles = (B + NB - 1) / NB;
    const int grid = (nTiles < GRID) ? nTiles : GRID;

    cudaFuncSetAttribute(smpl_fk_kernel,
                         cudaFuncAttributePreferredSharedMemoryCarveout, 100);
    smpl_fk_kernel<<<grid, 32>>>(orient, out, B);
}